// round 8
// baseline (speedup 1.0000x reference)
#include <cuda_runtime.h>
#include <cstdint>

#define BB 8192      // batch rows
#define NN 4096      // feature dim
#define PADF 68      // smem row pitch in floats (16B-aligned, conflict-free)

// 128 MB scratch for the intermediate (B, 4096) tensor (permuted layout).
__device__ float g_scratch[(size_t)BB * NN];

__device__ __forceinline__ uint32_t f2tf32(float f) {
    uint32_t r;
    asm("cvt.rna.tf32.f32 %0, %1;" : "=r"(r) : "f"(f));
    return r;
}

__device__ __forceinline__ void mma16n8k8(float* d, const uint32_t* a,
                                          uint32_t b0, uint32_t b1) {
    asm volatile(
        "mma.sync.aligned.m16n8k8.row.col.f32.tf32.tf32.f32 "
        "{%0,%1,%2,%3}, {%4,%5,%6,%7}, {%8,%9}, {%0,%1,%2,%3};"
        : "+f"(d[0]), "+f"(d[1]), "+f"(d[2]), "+f"(d[3])
        : "r"(a[0]), "r"(a[1]), "r"(a[2]), "r"(a[3]), "r"(b0), "r"(b1));
}

// ---------------------------------------------------------------------------
// R3-champion GEMM engine with permuted (scatter) epilogue.
//   CTA = 128 rows x one 64x64 block j.   blockIdx.x = j (wave locality!),
//   blockIdx.y = row tile.
//   compute: acc[b, q] = sum_p A[(m0+b)*4096 + j*64 + p] * W[j, q, p]
//   write:   C[(m0+b)*4096 + q*64 + j]    (4B stores, stride 256B;
//            sectors completed in L2 by the 8 adjacent-j CTAs co-resident
//            in the same wave)
// This single kernel implements both stages:
//   stage 1 (j=k): out1p[b, q*64+k] = sum_p x[b,k*64+p] w1[k,q,p]
//                  == perm[b, l*64+r] with l=q, r=k  (transpose fused)
//   stage 2 (j=l): reads perm naturally at cols l*64+r, writes
//                  out[b, s*64+l]  (final transpose fused)
// ---------------------------------------------------------------------------
__global__ __launch_bounds__(128) void gemm_perm(const float* __restrict__ A,
                                                 const float* __restrict__ W,
                                                 float* __restrict__ C) {
    extern __shared__ __align__(16) uint32_t sm[];
    uint32_t* As = sm;                 // 128 * 68
    uint32_t* Ws = sm + 128 * PADF;    //  64 * 68

    const int tid  = threadIdx.x;
    const int warp = tid >> 5;
    const int lane = tid & 31;
    const int g    = lane >> 2;
    const int t    = lane & 3;
    const int j    = blockIdx.x;           // block index (fast-varying!)
    const int m0   = blockIdx.y * 128;     // row tile

    // ---- load A tile (coalesced float4), convert to tf32 ----
    {
        const float* Ag = A + (size_t)m0 * NN + j * 64;
#pragma unroll
        for (int i = 0; i < 16; i++) {
            const int g4  = tid + i * 128;
            const int row = g4 >> 4;
            const int c4  = (g4 & 15) * 4;
            const float4 v = *(const float4*)(Ag + (size_t)row * NN + c4);
            uint32_t* d = As + row * PADF + c4;
            d[0] = f2tf32(v.x); d[1] = f2tf32(v.y);
            d[2] = f2tf32(v.z); d[3] = f2tf32(v.w);
        }
    }
    // ---- load W tile ----
    {
        const float* Wg = W + (size_t)j * 4096;
#pragma unroll
        for (int i = 0; i < 8; i++) {
            const int g4 = tid + i * 128;
            const int q  = g4 >> 4;
            const int c4 = (g4 & 15) * 4;
            const float4 v = *(const float4*)(Wg + q * 64 + c4);
            uint32_t* d = Ws + q * PADF + c4;
            d[0] = f2tf32(v.x); d[1] = f2tf32(v.y);
            d[2] = f2tf32(v.z); d[3] = f2tf32(v.w);
        }
    }
    __syncthreads();

    // ---- main loop (R3 champion): warp tile 32(M) x 64(N) ----
    float acc[2][8][4] = {};
    const int rb0 = warp * 32;
#pragma unroll
    for (int ks = 0; ks < 8; ks++) {
        const int k0 = ks * 8;
        uint32_t a[2][4];
#pragma unroll
        for (int mi = 0; mi < 2; mi++) {
            const int rb = rb0 + mi * 16;
            a[mi][0] = As[(rb + g)     * PADF + k0 + t];
            a[mi][1] = As[(rb + g + 8) * PADF + k0 + t];
            a[mi][2] = As[(rb + g)     * PADF + k0 + t + 4];
            a[mi][3] = As[(rb + g + 8) * PADF + k0 + t + 4];
        }
#pragma unroll
        for (int ni = 0; ni < 8; ni++) {
            const uint32_t b0 = Ws[(ni * 8 + g) * PADF + k0 + t];
            const uint32_t b1 = Ws[(ni * 8 + g) * PADF + k0 + t + 4];
            mma16n8k8(acc[0][ni], a[0], b0, b1);
            mma16n8k8(acc[1][ni], a[1], b0, b1);
        }
    }

    // ---- permuted scatter epilogue: C[b, q*64 + j] ----
    // 4B stores at stride 256B; adjacent-j CTAs in the same wave complete
    // each 32B sector inside L2 before writeback.
    float* Cg = C + j;
#pragma unroll
    for (int mi = 0; mi < 2; mi++) {
        const int r0 = rb0 + mi * 16 + g;
        const size_t base0 = (size_t)(m0 + r0) * NN;
        const size_t base1 = (size_t)(m0 + r0 + 8) * NN;
#pragma unroll
        for (int ni = 0; ni < 8; ni++) {
            const int q = ni * 8 + t * 2;
            Cg[base0 + (size_t)q * 64]       = acc[mi][ni][0];
            Cg[base0 + (size_t)(q + 1) * 64] = acc[mi][ni][1];
            Cg[base1 + (size_t)q * 64]       = acc[mi][ni][2];
            Cg[base1 + (size_t)(q + 1) * 64] = acc[mi][ni][3];
        }
    }
}

extern "C" void kernel_launch(void* const* d_in, const int* in_sizes, int n_in,
                              void* d_out, int out_size) {
    const float* x  = (const float*)d_in[0];   // (8192, 4096)
    const float* w1 = (const float*)d_in[1];   // (64, 64, 64)
    const float* w2 = (const float*)d_in[2];   // (64, 64, 64)
    float* out = (float*)d_out;

    float* scratch = nullptr;
    cudaGetSymbolAddress((void**)&scratch, g_scratch);

    const int smem_bytes = (128 * PADF + 64 * PADF) * 4;   // 52224
    cudaFuncSetAttribute(gemm_perm, cudaFuncAttributeMaxDynamicSharedMemorySize,
                         smem_bytes);

    dim3 grid(64, BB / 128);   // x = block index j (wave-local), y = row tile

    // Stage 1: perm[b, q*64+k] = sum_p x[b, k*64+p] * w1[k, q, p]
    //          (mid-permutation fused into the scatter write)
    gemm_perm<<<grid, 128, smem_bytes>>>(x, w1, scratch);

    // Stage 2: out[b, s*64+l] = sum_r perm[b, l*64+r] * w2[l, s, r]
    //          (final permutation fused into the scatter write)
    gemm_perm<<<grid, 128, smem_bytes>>>(scratch, w2, out);
}

// round 9
// speedup vs baseline: 2.3672x; 2.3672x over previous
#include <cuda_runtime.h>
#include <cstdint>

#define BB 8192      // batch rows
#define NN 4096      // feature dim
#define PADF 68      // stage-1 smem row pitch (floats)

// 128 MB scratch for the intermediate (B, 4096) tensor (natural layout).
__device__ float g_scratch[(size_t)BB * NN];

__device__ __forceinline__ uint32_t f2tf32(float f) {
    uint32_t r;
    asm("cvt.rna.tf32.f32 %0, %1;" : "=r"(r) : "f"(f));
    return r;
}

__device__ __forceinline__ void mma16n8k8(float* d, const uint32_t* a,
                                          uint32_t b0, uint32_t b1) {
    asm volatile(
        "mma.sync.aligned.m16n8k8.row.col.f32.tf32.tf32.f32 "
        "{%0,%1,%2,%3}, {%4,%5,%6,%7}, {%8,%9}, {%0,%1,%2,%3};"
        : "+f"(d[0]), "+f"(d[1]), "+f"(d[2]), "+f"(d[3])
        : "r"(a[0]), "r"(a[1]), "r"(a[2]), "r"(a[3]), "r"(b0), "r"(b1));
}

// ---------------------------------------------------------------------------
// Stage 1 (R3 champion, unchanged): CTA = 128 rows x one 64x64 block (j=k).
//   C[(m0+b)*4096 + k*64 + q] = sum_p A[(m0+b)*4096 + k*64 + p] * W[k, q, p]
// ---------------------------------------------------------------------------
__global__ __launch_bounds__(128) void gemm_mma(const float* __restrict__ A,
                                                const float* __restrict__ W,
                                                float* __restrict__ C) {
    extern __shared__ __align__(16) uint32_t sm[];
    uint32_t* As = sm;                 // 128 * 68
    uint32_t* Ws = sm + 128 * PADF;    //  64 * 68

    const int tid  = threadIdx.x;
    const int warp = tid >> 5;
    const int lane = tid & 31;
    const int g    = lane >> 2;
    const int t    = lane & 3;
    const int m0   = blockIdx.x * 128;
    const int j    = blockIdx.y;

    {
        const float* Ag = A + (size_t)m0 * NN + j * 64;
#pragma unroll
        for (int i = 0; i < 16; i++) {
            const int g4  = tid + i * 128;
            const int row = g4 >> 4;
            const int c4  = (g4 & 15) * 4;
            const float4 v = *(const float4*)(Ag + (size_t)row * NN + c4);
            uint32_t* d = As + row * PADF + c4;
            d[0] = f2tf32(v.x); d[1] = f2tf32(v.y);
            d[2] = f2tf32(v.z); d[3] = f2tf32(v.w);
        }
    }
    {
        const float* Wg = W + (size_t)j * 4096;
#pragma unroll
        for (int i = 0; i < 8; i++) {
            const int g4 = tid + i * 128;
            const int q  = g4 >> 4;
            const int c4 = (g4 & 15) * 4;
            const float4 v = *(const float4*)(Wg + q * 64 + c4);
            uint32_t* d = Ws + q * PADF + c4;
            d[0] = f2tf32(v.x); d[1] = f2tf32(v.y);
            d[2] = f2tf32(v.z); d[3] = f2tf32(v.w);
        }
    }
    __syncthreads();

    float acc[2][8][4] = {};
    const int rb0 = warp * 32;
#pragma unroll
    for (int ks = 0; ks < 8; ks++) {
        const int k0 = ks * 8;
        uint32_t a[2][4];
#pragma unroll
        for (int mi = 0; mi < 2; mi++) {
            const int rb = rb0 + mi * 16;
            a[mi][0] = As[(rb + g)     * PADF + k0 + t];
            a[mi][1] = As[(rb + g + 8) * PADF + k0 + t];
            a[mi][2] = As[(rb + g)     * PADF + k0 + t + 4];
            a[mi][3] = As[(rb + g + 8) * PADF + k0 + t + 4];
        }
#pragma unroll
        for (int ni = 0; ni < 8; ni++) {
            const uint32_t b0 = Ws[(ni * 8 + g) * PADF + k0 + t];
            const uint32_t b1 = Ws[(ni * 8 + g) * PADF + k0 + t + 4];
            mma16n8k8(acc[0][ni], a[0], b0, b1);
            mma16n8k8(acc[1][ni], a[1], b0, b1);
        }
    }

    float* Cg = C + (size_t)m0 * NN + j * 64;
#pragma unroll
    for (int mi = 0; mi < 2; mi++) {
        const int r0 = rb0 + mi * 16 + g;
#pragma unroll
        for (int ni = 0; ni < 8; ni++) {
            const int col = ni * 8 + t * 2;
            *(float2*)(Cg + (size_t)r0 * NN + col) =
                make_float2(acc[mi][ni][0], acc[mi][ni][1]);
            *(float2*)(Cg + (size_t)(r0 + 8) * NN + col) =
                make_float2(acc[mi][ni][2], acc[mi][ni][3]);
        }
    }
}

// ---------------------------------------------------------------------------
// Stage 2 fully fused, weights-in-registers.
//   perm[b, l*64+r] = out1[b, r*64+l]      (32B-chunk permuted read)
//   out2[b, l, s]   = sum_r perm * w2[l,s,r]
//   out[b, s*64+l]  = out2[b, l, s]        (32B-chunk permuted write)
// CTA: 128 rows x 8 l-blocks, 512 threads = 16 warps = (lw 0..7, nh 0..1).
// Warp tile 16(M=b) x 32(N=s); B fragments (64 regs/thread) loaded ONCE.
// Smem: A double buffer 2*32KB + staging 32KB = 96KB; A layout
//   word(b, l, r) = b*512 + l*64 + (r ^ 4*(b&7))   (conflict-free both sides)
// Staging layout word(b, dl, s) = b*512 + dl*64 + (s ^ 8*(b&7)).
// 8 chunks of 16 rows, LDG(c+1) overlaps MMA(c).
// ---------------------------------------------------------------------------
#define S2_CH    16
#define S2_NCH   8
#define S2_BUFW  8192                   // words per 32KB region
#define S2_SMEM  (3 * S2_BUFW * 4)      // 98304 bytes

__global__ __launch_bounds__(512) void s2_fused(const float* __restrict__ A,
                                                const float* __restrict__ W,
                                                float* __restrict__ out) {
    extern __shared__ __align__(16) uint32_t sm[];
    uint32_t* buf0 = sm;
    uint32_t* buf1 = sm + S2_BUFW;
    float*    ST   = (float*)(sm + 2 * S2_BUFW);

    const int tid  = threadIdx.x;
    const int warp = tid >> 5;
    const int lane = tid & 31;
    const int g    = lane >> 2;          // 0..7
    const int t    = lane & 3;           // 0..3
    const int lw   = warp >> 1;          // l within group (0..7)
    const int nh   = warp & 1;           // n half (0..1)
    const int l0   = blockIdx.x * 8;     // l-group (fast-varying: sector sharing)
    const int row0 = blockIdx.y * (S2_CH * S2_NCH);

    // ---- load B fragments into registers (once): w2[l0+lw, s, r] ----
    uint32_t breg[4][8][2];
    {
        const float* Wb = W + (size_t)(l0 + lw) * 4096 + (nh * 32 + g) * 64;
#pragma unroll
        for (int ni = 0; ni < 4; ni++) {
            const float* wr = Wb + ni * 8 * 64;
#pragma unroll
            for (int ks = 0; ks < 8; ks++) {
                breg[ni][ks][0] = f2tf32(wr[ks * 8 + t]);
                breg[ni][ks][1] = f2tf32(wr[ks * 8 + t + 4]);
            }
        }
    }

    // per-thread (b, r) assignments: 1024 32B-chunks per 16-row chunk, 2 each
    const int b0c = tid >> 6;            // 0..7  (i=0)
    const int r0c = tid & 63;            // i=0 and i=1 share r, b differs by 8
    // prefetch chunk 0
    float4 v[2][2];
#pragma unroll
    for (int i = 0; i < 2; i++) {
        const float* p = A + (size_t)(row0 + b0c + i * 8) * NN + r0c * 64 + l0;
        v[i][0] = *(const float4*)(p);
        v[i][1] = *(const float4*)(p + 4);
    }

    for (int c = 0; c < S2_NCH; c++) {
        uint32_t* cur = (c & 1) ? buf1 : buf0;

        // ---- STS chunk c (tf32 convert; scatter over l, conflict-free) ----
#pragma unroll
        for (int i = 0; i < 2; i++) {
            const int b = b0c + i * 8;
            uint32_t* d = cur + b * 512 + (r0c ^ (4 * (b & 7)));
            d[0 * 64] = f2tf32(v[i][0].x);
            d[1 * 64] = f2tf32(v[i][0].y);
            d[2 * 64] = f2tf32(v[i][0].z);
            d[3 * 64] = f2tf32(v[i][0].w);
            d[4 * 64] = f2tf32(v[i][1].x);
            d[5 * 64] = f2tf32(v[i][1].y);
            d[6 * 64] = f2tf32(v[i][1].z);
            d[7 * 64] = f2tf32(v[i][1].w);
        }
        // ---- prefetch chunk c+1 (overlaps MMA after the sync) ----
        if (c + 1 < S2_NCH) {
            const int rb = row0 + (c + 1) * S2_CH;
#pragma unroll
            for (int i = 0; i < 2; i++) {
                const float* p = A + (size_t)(rb + b0c + i * 8) * NN + r0c * 64 + l0;
                v[i][0] = *(const float4*)(p);
                v[i][1] = *(const float4*)(p + 4);
            }
        }
        __syncthreads();   // chunk c visible; staging free (prev STG done)

        // ---- MMA: warp (lw, nh), tile 16(b) x 32(s), K = 64 ----
        const uint32_t* Aw = cur + lw * 64;
        float acc[4][4] = {};
#pragma unroll
        for (int ks = 0; ks < 8; ks++) {
            const int k0 = ks * 8;
            uint32_t a[4];
            a[0] = Aw[(g)     * 512 + ((k0 + t)     ^ (4 * g))];
            a[1] = Aw[(g + 8) * 512 + ((k0 + t)     ^ (4 * g))];
            a[2] = Aw[(g)     * 512 + ((k0 + t + 4) ^ (4 * g))];
            a[3] = Aw[(g + 8) * 512 + ((k0 + t + 4) ^ (4 * g))];
#pragma unroll
            for (int ni = 0; ni < 4; ni++)
                mma16n8k8(acc[ni], a, breg[ni][ks][0], breg[ni][ks][1]);
        }
        __syncthreads();   // all warps done reading cur (safe to reuse @ c+2)

        // ---- stage accumulators: ST[b][dl=lw][s] (b-swizzled) ----
#pragma unroll
        for (int ni = 0; ni < 4; ni++) {
            const int s = nh * 32 + ni * 8 + t * 2;
            *(float2*)(ST + (g)     * 512 + lw * 64 + (s ^ (8 * (g & 7)))) =
                make_float2(acc[ni][0], acc[ni][1]);
            *(float2*)(ST + (g + 8) * 512 + lw * 64 + (s ^ (8 * (g & 7)))) =
                make_float2(acc[ni][2], acc[ni][3]);
        }
        __syncthreads();   // staging visible

        // ---- permuted 32B-chunk write: out[b, s*64 + l0..l0+7] ----
        const int brow = row0 + c * S2_CH;
#pragma unroll
        for (int i = 0; i < 2; i++) {
            const int b = b0c + i * 8;
            const int s = r0c;                       // reuse 0..63 mapping
            const float* p = ST + b * 512 + (s ^ (8 * (b & 7)));
            float4 o0 = make_float4(p[0 * 64], p[1 * 64], p[2 * 64], p[3 * 64]);
            float4 o1 = make_float4(p[4 * 64], p[5 * 64], p[6 * 64], p[7 * 64]);
            float* q = out + (size_t)(brow + b) * NN + s * 64 + l0;
            *(float4*)(q)     = o0;
            *(float4*)(q + 4) = o1;
        }
    }
}

extern "C" void kernel_launch(void* const* d_in, const int* in_sizes, int n_in,
                              void* d_out, int out_size) {
    const float* x  = (const float*)d_in[0];   // (8192, 4096)
    const float* w1 = (const float*)d_in[1];   // (64, 64, 64)
    const float* w2 = (const float*)d_in[2];   // (64, 64, 64)
    float* out = (float*)d_out;

    float* scratch = nullptr;
    cudaGetSymbolAddress((void**)&scratch, g_scratch);

    const int smem1 = (128 * PADF + 64 * PADF) * 4;   // 52224
    cudaFuncSetAttribute(gemm_mma, cudaFuncAttributeMaxDynamicSharedMemorySize, smem1);
    cudaFuncSetAttribute(s2_fused, cudaFuncAttributeMaxDynamicSharedMemorySize, S2_SMEM);

    // Stage 1: out1[b, k*64+q] = sum_p x[b, k*64+p] * w1[k, q, p]  (natural)
    dim3 g1(BB / 128, 64);
    gemm_mma<<<g1, 128, smem1>>>(x, w1, scratch);

    // Stage 2: fused permute-in + GEMM + permute-out
    dim3 g2(64 / 8, BB / (S2_CH * S2_NCH));    // (8, 64) — lg fast-varying
    s2_fused<<<g2, 512, S2_SMEM>>>(scratch, w2, out);
}

// round 10
// speedup vs baseline: 2.9113x; 1.2298x over previous
#include <cuda_runtime.h>
#include <cstdint>

#define BB 8192      // batch rows
#define NN 4096      // feature dim
#define TPC 4        // m-tiles (128 rows) per CTA, pipelined

// 128 MB scratch for the intermediate (B, 4096) tensor.
__device__ float g_scratch[(size_t)BB * NN];

__device__ __forceinline__ uint32_t f2tf32(float f) {
    uint32_t r;
    asm("cvt.rna.tf32.f32 %0, %1;" : "=r"(r) : "f"(f));
    return r;
}

__device__ __forceinline__ void mma16n8k8(float* d, const uint32_t* a,
                                          uint32_t b0, uint32_t b1) {
    asm volatile(
        "mma.sync.aligned.m16n8k8.row.col.f32.tf32.tf32.f32 "
        "{%0,%1,%2,%3}, {%4,%5,%6,%7}, {%8,%9}, {%0,%1,%2,%3};"
        : "+f"(d[0]), "+f"(d[1]), "+f"(d[2]), "+f"(d[3])
        : "r"(a[0]), "r"(a[1]), "r"(a[2]), "r"(a[3]), "r"(b0), "r"(b1));
}

// ---------------------------------------------------------------------------
// Pipelined block GEMM: CTA = one 64x64 block j  x  TPC tiles of 128 rows.
//   C[(m)*4096 + j*64 + q] = sum_p A[(m)*4096 + j*64 + p] * W[j, q, p]
// Smem (tight XOR-4 swizzle, word(row,k) = row*64 + (k ^ 4*(row&7))):
//   A double buffer 2 x 128x64 (2x32KB) + W 64x64 (16KB) = 80KB -> 2 CTA/SM.
// Pipeline per tile c: STS(c from regs) ; LDG(c+1 -> regs) ; sync ;
//   MMA(c) ; STG(c).  One barrier per tile (buffers alternate; the barrier
//   at tile c orders all warps' MMA(c-1) before any STS into that buffer
//   at tile c+1).
// Swizzle conflict-free for STS.128 and all MMA fragment LDS (bank =
//   ((k0+t) ^ 4g) mod 32 spans 32 distinct banks; proven R6/R7).
// In-place safe (A==C): CTA row-range x column-block regions are disjoint
// across CTAs; within a CTA, tile c+1 reads and tile c writes target
// disjoint rows.
// ---------------------------------------------------------------------------
__global__ __launch_bounds__(128) void gemm_pipe(const float* __restrict__ A,
                                                 const float* __restrict__ W,
                                                 float* __restrict__ C) {
    extern __shared__ __align__(16) uint32_t sm[];
    uint32_t* Ab0 = sm;               // 8192 words
    uint32_t* Ab1 = sm + 8192;        // 8192 words
    uint32_t* Ws  = sm + 16384;       // 4096 words

    const int tid   = threadIdx.x;
    const int warp  = tid >> 5;
    const int lane  = tid & 31;
    const int g     = lane >> 2;       // 0..7
    const int t     = lane & 3;        // 0..3
    const int j     = blockIdx.y;
    const int mbase = blockIdx.x * (128 * TPC);

    // ---- load W once (tf32, swizzled) ----
    {
        const float* Wg = W + (size_t)j * 4096;
#pragma unroll
        for (int i = 0; i < 8; i++) {
            const int g4 = tid + i * 128;      // 0..1023 float4s
            const int q  = g4 >> 4;
            const int c4 = (g4 & 15) * 4;
            const float4 v = *(const float4*)(Wg + q * 64 + c4);
            uint32_t* d = Ws + q * 64 + (c4 ^ (4 * (q & 7)));
            d[0] = f2tf32(v.x); d[1] = f2tf32(v.y);
            d[2] = f2tf32(v.z); d[3] = f2tf32(v.w);
        }
    }

    // per-thread A-load coordinates (16 float4s per 128x64 tile)
    int rowv[16], colv[16];
#pragma unroll
    for (int i = 0; i < 16; i++) {
        const int g4 = tid + i * 128;
        rowv[i] = g4 >> 4;
        colv[i] = (g4 & 15) * 4;
    }

    // ---- prefetch tile 0 ----
    float4 v[16];
#pragma unroll
    for (int i = 0; i < 16; i++)
        v[i] = *(const float4*)(A + (size_t)(mbase + rowv[i]) * NN + j * 64 + colv[i]);

    const int rb0 = warp * 32;

    for (int c = 0; c < TPC; c++) {
        uint32_t* cur = (c & 1) ? Ab1 : Ab0;

        // ---- STS tile c (tf32 convert, swizzled) ----
#pragma unroll
        for (int i = 0; i < 16; i++) {
            uint32_t* d = cur + rowv[i] * 64 + (colv[i] ^ (4 * (rowv[i] & 7)));
            d[0] = f2tf32(v[i].x); d[1] = f2tf32(v[i].y);
            d[2] = f2tf32(v[i].z); d[3] = f2tf32(v[i].w);
        }
        // ---- prefetch tile c+1 (overlaps MMA below) ----
        if (c + 1 < TPC) {
            const int mb = mbase + (c + 1) * 128;
#pragma unroll
            for (int i = 0; i < 16; i++)
                v[i] = *(const float4*)(A + (size_t)(mb + rowv[i]) * NN + j * 64 + colv[i]);
        }
        __syncthreads();   // tile c visible; other buffer's readers done

        // ---- MMA: warp tile 32(M) x 64(N), K=64 ----
        float acc[2][8][4] = {};
#pragma unroll
        for (int ks = 0; ks < 8; ks++) {
            const int k0 = ks * 8;
            const int sa = 4 * g;
            uint32_t a[2][4];
#pragma unroll
            for (int mi = 0; mi < 2; mi++) {
                const int rb = rb0 + mi * 16;
                a[mi][0] = cur[(rb + g)     * 64 + ((k0 + t)     ^ sa)];
                a[mi][1] = cur[(rb + g + 8) * 64 + ((k0 + t)     ^ sa)];
                a[mi][2] = cur[(rb + g)     * 64 + ((k0 + t + 4) ^ sa)];
                a[mi][3] = cur[(rb + g + 8) * 64 + ((k0 + t + 4) ^ sa)];
            }
#pragma unroll
            for (int ni = 0; ni < 8; ni++) {
                const uint32_t b0 = Ws[(ni * 8 + g) * 64 + ((k0 + t)     ^ sa)];
                const uint32_t b1 = Ws[(ni * 8 + g) * 64 + ((k0 + t + 4) ^ sa)];
                mma16n8k8(acc[0][ni], a[0], b0, b1);
                mma16n8k8(acc[1][ni], a[1], b0, b1);
            }
        }

        // ---- STG tile c (sector-exact float2) ----
        float* Cg = C + (size_t)(mbase + c * 128) * NN + j * 64;
#pragma unroll
        for (int mi = 0; mi < 2; mi++) {
            const int r0 = rb0 + mi * 16 + g;
#pragma unroll
            for (int ni = 0; ni < 8; ni++) {
                const int col = ni * 8 + t * 2;
                *(float2*)(Cg + (size_t)r0 * NN + col) =
                    make_float2(acc[mi][ni][0], acc[mi][ni][1]);
                *(float2*)(Cg + (size_t)(r0 + 8) * NN + col) =
                    make_float2(acc[mi][ni][2], acc[mi][ni][3]);
            }
        }
    }
}

// ---------------------------------------------------------------------------
// Per-row 64x64 transpose: out[b, i*64 + j] = in[b, j*64 + i]. In-place safe.
// (70% of HBM spec; unchanged champion.)
// ---------------------------------------------------------------------------
__global__ __launch_bounds__(256) void trans64(const float* __restrict__ in,
                                               float* __restrict__ out) {
    __shared__ float smt[64][65];
    const int b   = blockIdx.x;
    const int tid = threadIdx.x;
    const float* ip = in  + (size_t)b * NN;
    float*       op = out + (size_t)b * NN;

#pragma unroll
    for (int i = 0; i < 16; i++) {
        const int t = tid + i * 256;
        smt[t & 63][t >> 6] = ip[t];
    }
    __syncthreads();
#pragma unroll
    for (int i = 0; i < 16; i++) {
        const int t = tid + i * 256;
        op[t] = smt[t >> 6][t & 63];
    }
}

extern "C" void kernel_launch(void* const* d_in, const int* in_sizes, int n_in,
                              void* d_out, int out_size) {
    const float* x  = (const float*)d_in[0];   // (8192, 4096)
    const float* w1 = (const float*)d_in[1];   // (64, 64, 64)
    const float* w2 = (const float*)d_in[2];   // (64, 64, 64)
    float* out = (float*)d_out;

    float* scratch = nullptr;
    cudaGetSymbolAddress((void**)&scratch, g_scratch);

    const int smem_bytes = (2 * 8192 + 4096) * 4;   // 81920
    cudaFuncSetAttribute(gemm_pipe, cudaFuncAttributeMaxDynamicSharedMemorySize,
                         smem_bytes);

    dim3 ggrid(BB / (128 * TPC), 64);   // (16, 64) = 1024 CTAs

    // Stage 1: out1[b, k*64+q] = sum_p x[b, k*64+p] * w1[k, q, p]
    gemm_pipe<<<ggrid, 128, smem_bytes>>>(x, w1, scratch);
    // Permutation: (b, r*64+l) -> (b, l*64+r)
    trans64<<<BB, 256>>>(scratch, scratch);
    // Stage 2: out2[b, l*64+s] = sum_r perm[b, l*64+r] * w2[l, s, r]
    gemm_pipe<<<ggrid, 128, smem_bytes>>>(scratch, w2, scratch);
    // Final permutation: out[b, s*64+l] = out2[b, l*64+s]
    trans64<<<BB, 256>>>(scratch, out);
}

// round 11
// speedup vs baseline: 3.2880x; 1.1294x over previous
#include <cuda_runtime.h>
#include <cstdint>

#define BB 8192      // batch rows
#define NN 4096      // feature dim
#define TPC 4        // 128-row tiles per CTA, pipelined

// Feature-major intermediate: S5[f][b], f = k*64+q, shape (4096, 8192). 128MB.
__device__ float g_S5[(size_t)NN * BB];
// Natural-layout stage-2 output (b, l*64+s). 128MB.
__device__ float g_out2[(size_t)BB * NN];

__device__ __forceinline__ uint32_t f2tf32(float f) {
    uint32_t r;
    asm("cvt.rna.tf32.f32 %0, %1;" : "=r"(r) : "f"(f));
    return r;
}

__device__ __forceinline__ void mma16n8k8(float* d, const uint32_t* a,
                                          uint32_t b0, uint32_t b1) {
    asm volatile(
        "mma.sync.aligned.m16n8k8.row.col.f32.tf32.tf32.f32 "
        "{%0,%1,%2,%3}, {%4,%5,%6,%7}, {%8,%9}, {%0,%1,%2,%3};"
        : "+f"(d[0]), "+f"(d[1]), "+f"(d[2]), "+f"(d[3])
        : "r"(a[0]), "r"(a[1]), "r"(a[2]), "r"(a[3]), "r"(b0), "r"(b1));
}

// ---------------------------------------------------------------------------
// Stage 1: natural read of x, pipelined GEMM, FEATURE-MAJOR write.
//   S5[(k*64+q)*8192 + b] = sum_p x[b, k*64+p] * w1[k, q, p]
// CTA = block k (blockIdx.y) x TPC tiles of 128 rows.
// Smem: A double buffer 2 x 8448 words + W 4096 words = 84992B -> 2 CTA/SM.
//   A-tile layout: word(row,p) = row*64 + (p ^ 4*(row&7))   (R10-proven)
//   epilogue staging reuses 'cur': st[q*132 + b']  (bank 8t+g+16mi: clean)
// ---------------------------------------------------------------------------
#define ABW 8448   // A buffer words (>= 8192 tile, >= 64*132 staging)

__global__ __launch_bounds__(128) void gemm_s1(const float* __restrict__ A,
                                               const float* __restrict__ W,
                                               float* __restrict__ S5) {
    extern __shared__ __align__(16) uint32_t sm[];
    uint32_t* Ab0 = sm;
    uint32_t* Ab1 = sm + ABW;
    uint32_t* Ws  = sm + 2 * ABW;      // 4096 words

    const int tid   = threadIdx.x;
    const int warp  = tid >> 5;
    const int lane  = tid & 31;
    const int g     = lane >> 2;
    const int t     = lane & 3;
    const int j     = blockIdx.y;                 // k block
    const int mbase = blockIdx.x * (128 * TPC);

    // ---- load W once (tf32, swizzled) ----
    {
        const float* Wg = W + (size_t)j * 4096;
#pragma unroll
        for (int i = 0; i < 8; i++) {
            const int g4 = tid + i * 128;
            const int q  = g4 >> 4;
            const int c4 = (g4 & 15) * 4;
            const float4 v = *(const float4*)(Wg + q * 64 + c4);
            uint32_t* d = Ws + q * 64 + (c4 ^ (4 * (q & 7)));
            d[0] = f2tf32(v.x); d[1] = f2tf32(v.y);
            d[2] = f2tf32(v.z); d[3] = f2tf32(v.w);
        }
    }

    int rowv[16], colv[16];
#pragma unroll
    for (int i = 0; i < 16; i++) {
        const int g4 = tid + i * 128;
        rowv[i] = g4 >> 4;
        colv[i] = (g4 & 15) * 4;
    }

    // prefetch tile 0
    float4 v[16];
#pragma unroll
    for (int i = 0; i < 16; i++)
        v[i] = *(const float4*)(A + (size_t)(mbase + rowv[i]) * NN + j * 64 + colv[i]);

    const int rb0 = warp * 32;

    for (int c = 0; c < TPC; c++) {
        uint32_t* cur = (c & 1) ? Ab1 : Ab0;

        // ---- STS tile c ----
#pragma unroll
        for (int i = 0; i < 16; i++) {
            uint32_t* d = cur + rowv[i] * 64 + (colv[i] ^ (4 * (rowv[i] & 7)));
            d[0] = f2tf32(v[i].x); d[1] = f2tf32(v[i].y);
            d[2] = f2tf32(v[i].z); d[3] = f2tf32(v[i].w);
        }
        // ---- prefetch tile c+1 ----
        if (c + 1 < TPC) {
            const int mb = mbase + (c + 1) * 128;
#pragma unroll
            for (int i = 0; i < 16; i++)
                v[i] = *(const float4*)(A + (size_t)(mb + rowv[i]) * NN + j * 64 + colv[i]);
        }
        __syncthreads();   // (1) tile c visible

        // ---- MMA: warp tile 32(M) x 64(N) ----
        float acc[2][8][4] = {};
#pragma unroll
        for (int ks = 0; ks < 8; ks++) {
            const int k0 = ks * 8;
            const int sa = 4 * g;
            uint32_t a[2][4];
#pragma unroll
            for (int mi = 0; mi < 2; mi++) {
                const int rb = rb0 + mi * 16;
                a[mi][0] = cur[(rb + g)     * 64 + ((k0 + t)     ^ sa)];
                a[mi][1] = cur[(rb + g + 8) * 64 + ((k0 + t)     ^ sa)];
                a[mi][2] = cur[(rb + g)     * 64 + ((k0 + t + 4) ^ sa)];
                a[mi][3] = cur[(rb + g + 8) * 64 + ((k0 + t + 4) ^ sa)];
            }
#pragma unroll
            for (int ni = 0; ni < 8; ni++) {
                const uint32_t b0 = Ws[(ni * 8 + g) * 64 + ((k0 + t)     ^ sa)];
                const uint32_t b1 = Ws[(ni * 8 + g) * 64 + ((k0 + t + 4) ^ sa)];
                mma16n8k8(acc[0][ni], a[0], b0, b1);
                mma16n8k8(acc[1][ni], a[1], b0, b1);
            }
        }
        __syncthreads();   // (2) all warps done reading cur -> reuse as staging

        // ---- stage accumulators q-major: st[q*132 + b'] ----
        float* st = (float*)cur;
#pragma unroll
        for (int mi = 0; mi < 2; mi++) {
            const int r0 = rb0 + mi * 16 + g;
#pragma unroll
            for (int ni = 0; ni < 8; ni++) {
                const int q = ni * 8 + t * 2;
                st[(q)     * 132 + r0]     = acc[mi][ni][0];
                st[(q + 1) * 132 + r0]     = acc[mi][ni][1];
                st[(q)     * 132 + r0 + 8] = acc[mi][ni][2];
                st[(q + 1) * 132 + r0 + 8] = acc[mi][ni][3];
            }
        }
        __syncthreads();   // (3) staging visible

        // ---- feature-major STG: S5[(j*64+q)*8192 + mb + b'] (512B runs) ----
        const int mb = mbase + c * 128;
#pragma unroll
        for (int i = 0; i < 16; i++) {
            const int idx = tid + i * 128;    // 0..2047
            const int q   = idx >> 5;
            const int bc  = (idx & 31) * 4;
            const float4 o = *(const float4*)(st + q * 132 + bc);
            *(float4*)(S5 + (size_t)(j * 64 + q) * BB + mb + bc) = o;
        }
    }
}

// ---------------------------------------------------------------------------
// Stage 2: FEATURE-MAJOR read (the mid-permutation, free), pipelined GEMM,
// natural write.
//   out2[b, l*64+s] = sum_r S5[(r*64+l)*8192 + b] * w2[l, s, r]
// CTA = block l (blockIdx.y) x TPC tiles of 128 rows.
// Smem: A K-major As[r*136 + b'] double buffer 2 x 8704 + W 4096 words
//   = 86016B -> 2 CTA/SM. Fragment bank = 8t+g+16mi: conflict-free.
// ---------------------------------------------------------------------------
#define ABW2 8704

__global__ __launch_bounds__(128) void gemm_s2(const float* __restrict__ S5,
                                               const float* __restrict__ W,
                                               float* __restrict__ C) {
    extern __shared__ __align__(16) uint32_t sm[];
    uint32_t* Ab0 = sm;
    uint32_t* Ab1 = sm + ABW2;
    uint32_t* Ws  = sm + 2 * ABW2;

    const int tid   = threadIdx.x;
    const int warp  = tid >> 5;
    const int lane  = tid & 31;
    const int g     = lane >> 2;
    const int t     = lane & 3;
    const int j     = blockIdx.y;                 // l block
    const int mbase = blockIdx.x * (128 * TPC);

    // ---- load W once: w2[l, s, r], swizzled Ws[s*64 + (r ^ 4*(s&7))] ----
    {
        const float* Wg = W + (size_t)j * 4096;
#pragma unroll
        for (int i = 0; i < 8; i++) {
            const int g4 = tid + i * 128;
            const int s  = g4 >> 4;
            const int c4 = (g4 & 15) * 4;
            const float4 v = *(const float4*)(Wg + s * 64 + c4);
            uint32_t* d = Ws + s * 64 + (c4 ^ (4 * (s & 7)));
            d[0] = f2tf32(v.x); d[1] = f2tf32(v.y);
            d[2] = f2tf32(v.z); d[3] = f2tf32(v.w);
        }
    }

    // per-thread A-load coords: 2048 float4s per tile; warp covers one r-row
    int rv[16], bcv[16];
#pragma unroll
    for (int i = 0; i < 16; i++) {
        const int idx = tid + i * 128;
        rv[i]  = idx >> 5;            // r 0..63
        bcv[i] = (idx & 31) * 4;      // b-chunk
    }

    // prefetch tile 0 (512B-coalesced rows of S5)
    float4 v[16];
#pragma unroll
    for (int i = 0; i < 16; i++)
        v[i] = *(const float4*)(S5 + (size_t)(rv[i] * 64 + j) * BB + mbase + bcv[i]);

    const int rb0 = warp * 32;

    for (int c = 0; c < TPC; c++) {
        uint32_t* cur = (c & 1) ? Ab1 : Ab0;

        // ---- STS tile c: K-major As[r*136 + b'] (natural float4) ----
#pragma unroll
        for (int i = 0; i < 16; i++) {
            uint32_t* d = cur + rv[i] * 136 + bcv[i];
            d[0] = f2tf32(v[i].x); d[1] = f2tf32(v[i].y);
            d[2] = f2tf32(v[i].z); d[3] = f2tf32(v[i].w);
        }
        // ---- prefetch tile c+1 ----
        if (c + 1 < TPC) {
            const int mb = mbase + (c + 1) * 128;
#pragma unroll
            for (int i = 0; i < 16; i++)
                v[i] = *(const float4*)(S5 + (size_t)(rv[i] * 64 + j) * BB + mb + bcv[i]);
        }
        __syncthreads();   // tile c visible; prior MMA readers of cur done

        // ---- MMA: warp tile 32(M=b) x 64(N=s); A from K-major layout ----
        float acc[2][8][4] = {};
#pragma unroll
        for (int ks = 0; ks < 8; ks++) {
            const int k0 = ks * 8;
            uint32_t a[2][4];
#pragma unroll
            for (int mi = 0; mi < 2; mi++) {
                const int rb = rb0 + mi * 16;
                a[mi][0] = cur[(k0 + t)     * 136 + rb + g];
                a[mi][1] = cur[(k0 + t)     * 136 + rb + g + 8];
                a[mi][2] = cur[(k0 + t + 4) * 136 + rb + g];
                a[mi][3] = cur[(k0 + t + 4) * 136 + rb + g + 8];
            }
            const int sa = 4 * g;
#pragma unroll
            for (int ni = 0; ni < 8; ni++) {
                const uint32_t b0 = Ws[(ni * 8 + g) * 64 + ((k0 + t)     ^ sa)];
                const uint32_t b1 = Ws[(ni * 8 + g) * 64 + ((k0 + t + 4) ^ sa)];
                mma16n8k8(acc[0][ni], a[0], b0, b1);
                mma16n8k8(acc[1][ni], a[1], b0, b1);
            }
        }

        // ---- natural STG (sector-exact float2): C[b, j*64+s] ----
        float* Cg = C + (size_t)(mbase + c * 128) * NN + j * 64;
#pragma unroll
        for (int mi = 0; mi < 2; mi++) {
            const int r0 = rb0 + mi * 16 + g;
#pragma unroll
            for (int ni = 0; ni < 8; ni++) {
                const int col = ni * 8 + t * 2;
                *(float2*)(Cg + (size_t)r0 * NN + col) =
                    make_float2(acc[mi][ni][0], acc[mi][ni][1]);
                *(float2*)(Cg + (size_t)(r0 + 8) * NN + col) =
                    make_float2(acc[mi][ni][2], acc[mi][ni][3]);
            }
        }
    }
}

// ---------------------------------------------------------------------------
// Final permutation: out[b, s*64 + l] = in[b, l*64 + s].  (70% HBM champion)
// ---------------------------------------------------------------------------
__global__ __launch_bounds__(256) void trans64(const float* __restrict__ in,
                                               float* __restrict__ out) {
    __shared__ float smt[64][65];
    const int b   = blockIdx.x;
    const int tid = threadIdx.x;
    const float* ip = in  + (size_t)b * NN;
    float*       op = out + (size_t)b * NN;

#pragma unroll
    for (int i = 0; i < 16; i++) {
        const int t = tid + i * 256;
        smt[t & 63][t >> 6] = ip[t];
    }
    __syncthreads();
#pragma unroll
    for (int i = 0; i < 16; i++) {
        const int t = tid + i * 256;
        op[t] = smt[t >> 6][t & 63];
    }
}

extern "C" void kernel_launch(void* const* d_in, const int* in_sizes, int n_in,
                              void* d_out, int out_size) {
    const float* x  = (const float*)d_in[0];   // (8192, 4096)
    const float* w1 = (const float*)d_in[1];   // (64, 64, 64)
    const float* w2 = (const float*)d_in[2];   // (64, 64, 64)
    float* out = (float*)d_out;

    float *S5 = nullptr, *out2 = nullptr;
    cudaGetSymbolAddress((void**)&S5, g_S5);
    cudaGetSymbolAddress((void**)&out2, g_out2);

    const int smem1 = (2 * ABW  + 4096) * 4;   // 84992
    const int smem2 = (2 * ABW2 + 4096) * 4;   // 86016
    cudaFuncSetAttribute(gemm_s1, cudaFuncAttributeMaxDynamicSharedMemorySize, smem1);
    cudaFuncSetAttribute(gemm_s2, cudaFuncAttributeMaxDynamicSharedMemorySize, smem2);

    dim3 ggrid(BB / (128 * TPC), 64);   // (16, 64)

    // Stage 1: x (natural) -> S5 (feature-major).  Mid-permutation absorbed.
    gemm_s1<<<ggrid, 128, smem1>>>(x, w1, S5);
    // Stage 2: S5 (feature-major read) -> out2 (natural (b, l*64+s)).
    gemm_s2<<<ggrid, 128, smem2>>>(S5, w2, out2);
    // Final permutation: out[b, s*64+l] = out2[b, l*64+s].
    trans64<<<BB, 256>>>(out2, out);
}

// round 12
// speedup vs baseline: 3.5438x; 1.0778x over previous
#include <cuda_runtime.h>
#include <cstdint>

#define BB 8192      // batch rows
#define NN 4096      // feature dim
#define TPC 4        // 128-row tiles per CTA, pipelined

// Feature-major intermediate: S5[f][b], f = k*64+q, shape (4096, 8192). 128MB.
__device__ float g_S5[(size_t)NN * BB];
// Natural-layout stage-2 output (b, l*64+s). 128MB.
__device__ float g_out2[(size_t)BB * NN];

__device__ __forceinline__ uint32_t f2tf32(float f) {
    uint32_t r;
    asm("cvt.rna.tf32.f32 %0, %1;" : "=r"(r) : "f"(f));
    return r;
}

__device__ __forceinline__ void mma16n8k8(float* d, const uint32_t* a,
                                          uint32_t b0, uint32_t b1) {
    asm volatile(
        "mma.sync.aligned.m16n8k8.row.col.f32.tf32.tf32.f32 "
        "{%0,%1,%2,%3}, {%4,%5,%6,%7}, {%8,%9}, {%0,%1,%2,%3};"
        : "+f"(d[0]), "+f"(d[1]), "+f"(d[2]), "+f"(d[3])
        : "r"(a[0]), "r"(a[1]), "r"(a[2]), "r"(a[3]), "r"(b0), "r"(b1));
}

// ---------------------------------------------------------------------------
// Stage 1 TRANSPOSED: M = q (64), N = b (128 per tile), K = p (64).
//   S5[(j*64+q)*8192 + b] = sum_p w1[j, q, p] * x[b, j*64+p]
// A-operand = w1 (row-major q x p): fragments cached in registers (areg),
//   loaded ONCE from smem -> zero A-side LDS in the main loop.
// B-operand = x tile (fragment[n=b][k=p] = x[b][p]) from swizzled smem.
// Epilogue: fragment (c0,c1) = consecutive b -> DIRECT float2 stores to
//   feature-major S5. No staging, 1 barrier per tile.
// Smem: X double buffer 2x8192 + W 4096 words = 80KB -> 2 CTA/SM.
// ---------------------------------------------------------------------------
__global__ __launch_bounds__(128) void gemm_s1t(const float* __restrict__ A,
                                                const float* __restrict__ W,
                                                float* __restrict__ S5) {
    extern __shared__ __align__(16) uint32_t sm[];
    uint32_t* Xb0 = sm;                // 8192 words
    uint32_t* Xb1 = sm + 8192;         // 8192 words
    uint32_t* Ws  = sm + 16384;        // 4096 words

    const int tid   = threadIdx.x;
    const int warp  = tid >> 5;
    const int lane  = tid & 31;
    const int g     = lane >> 2;       // 0..7
    const int t     = lane & 3;        // 0..3
    const int j     = blockIdx.y;      // k block
    const int mbase = blockIdx.x * (128 * TPC);

    // ---- load W1[j] (q x p) into smem, swizzled ----
    {
        const float* Wg = W + (size_t)j * 4096;
#pragma unroll
        for (int i = 0; i < 8; i++) {
            const int g4 = tid + i * 128;
            const int q  = g4 >> 4;
            const int c4 = (g4 & 15) * 4;
            const float4 v = *(const float4*)(Wg + q * 64 + c4);
            uint32_t* d = Ws + q * 64 + (c4 ^ (4 * (q & 7)));
            d[0] = f2tf32(v.x); d[1] = f2tf32(v.y);
            d[2] = f2tf32(v.z); d[3] = f2tf32(v.w);
        }
    }

    // per-thread x-load coords (16 float4s per 128x64 tile)
    int rowv[16], colv[16];
#pragma unroll
    for (int i = 0; i < 16; i++) {
        const int g4 = tid + i * 128;
        rowv[i] = g4 >> 4;             // b 0..127
        colv[i] = (g4 & 15) * 4;       // p chunk
    }

    // prefetch tile 0
    float4 v[16];
#pragma unroll
    for (int i = 0; i < 16; i++)
        v[i] = *(const float4*)(A + (size_t)(mbase + rowv[i]) * NN + j * 64 + colv[i]);

    __syncthreads();   // W visible

    // ---- cache A-fragments (weights) in registers: rows q = warp*16 + ... ----
    const int q0 = warp * 16;
    uint32_t areg[8][4];
    {
        const int sa = 4 * g;
#pragma unroll
        for (int ks = 0; ks < 8; ks++) {
            const int k0 = ks * 8;
            areg[ks][0] = Ws[(q0 + g)     * 64 + ((k0 + t)     ^ sa)];
            areg[ks][1] = Ws[(q0 + g + 8) * 64 + ((k0 + t)     ^ sa)];
            areg[ks][2] = Ws[(q0 + g)     * 64 + ((k0 + t + 4) ^ sa)];
            areg[ks][3] = Ws[(q0 + g + 8) * 64 + ((k0 + t + 4) ^ sa)];
        }
    }

    for (int c = 0; c < TPC; c++) {
        uint32_t* cur = (c & 1) ? Xb1 : Xb0;

        // ---- STS x tile c (tf32 convert, swizzled) ----
#pragma unroll
        for (int i = 0; i < 16; i++) {
            uint32_t* d = cur + rowv[i] * 64 + (colv[i] ^ (4 * (rowv[i] & 7)));
            d[0] = f2tf32(v[i].x); d[1] = f2tf32(v[i].y);
            d[2] = f2tf32(v[i].z); d[3] = f2tf32(v[i].w);
        }
        // ---- prefetch tile c+1 (overlaps MMA) ----
        if (c + 1 < TPC) {
            const int mb = mbase + (c + 1) * 128;
#pragma unroll
            for (int i = 0; i < 16; i++)
                v[i] = *(const float4*)(A + (size_t)(mb + rowv[i]) * NN + j * 64 + colv[i]);
        }
        __syncthreads();   // tile c visible; prior readers of cur done

        // ---- MMA: 64(q) x 128(b), K=64; A from regs, B from smem ----
        float acc[16][4] = {};
#pragma unroll
        for (int ks = 0; ks < 8; ks++) {
            const int k0 = ks * 8;
            const int sa = 4 * g;
            const uint32_t i0 = (k0 + t) ^ sa;
            const uint32_t i1 = (k0 + t + 4) ^ sa;
#pragma unroll
            for (int ni = 0; ni < 16; ni++) {
                const uint32_t b0 = cur[(ni * 8 + g) * 64 + i0];
                const uint32_t b1 = cur[(ni * 8 + g) * 64 + i1];
                mma16n8k8(acc[ni], areg[ks], b0, b1);
            }
        }

        // ---- DIRECT feature-major STG: S5[(j*64+q)*8192 + b] float2 ----
        const int mb = mbase + c * 128;
        float* R0 = S5 + (size_t)(j * 64 + q0 + g)     * BB + mb + 2 * t;
        float* R1 = S5 + (size_t)(j * 64 + q0 + g + 8) * BB + mb + 2 * t;
#pragma unroll
        for (int ni = 0; ni < 16; ni++) {
            *(float2*)(R0 + ni * 8) = make_float2(acc[ni][0], acc[ni][1]);
            *(float2*)(R1 + ni * 8) = make_float2(acc[ni][2], acc[ni][3]);
        }
    }
}

// ---------------------------------------------------------------------------
// Stage 2 (unchanged from R11): feature-major read, pipelined GEMM, natural
// write.   out2[b, l*64+s] = sum_r S5[(r*64+l)*8192 + b] * w2[l, s, r]
// ---------------------------------------------------------------------------
#define ABW2 8704

__global__ __launch_bounds__(128) void gemm_s2(const float* __restrict__ S5,
                                               const float* __restrict__ W,
                                               float* __restrict__ C) {
    extern __shared__ __align__(16) uint32_t sm[];
    uint32_t* Ab0 = sm;
    uint32_t* Ab1 = sm + ABW2;
    uint32_t* Ws  = sm + 2 * ABW2;

    const int tid   = threadIdx.x;
    const int warp  = tid >> 5;
    const int lane  = tid & 31;
    const int g     = lane >> 2;
    const int t     = lane & 3;
    const int j     = blockIdx.y;                 // l block
    const int mbase = blockIdx.x * (128 * TPC);

    // ---- load W once: w2[l, s, r], swizzled ----
    {
        const float* Wg = W + (size_t)j * 4096;
#pragma unroll
        for (int i = 0; i < 8; i++) {
            const int g4 = tid + i * 128;
            const int s  = g4 >> 4;
            const int c4 = (g4 & 15) * 4;
            const float4 v = *(const float4*)(Wg + s * 64 + c4);
            uint32_t* d = Ws + s * 64 + (c4 ^ (4 * (s & 7)));
            d[0] = f2tf32(v.x); d[1] = f2tf32(v.y);
            d[2] = f2tf32(v.z); d[3] = f2tf32(v.w);
        }
    }

    int rv[16], bcv[16];
#pragma unroll
    for (int i = 0; i < 16; i++) {
        const int idx = tid + i * 128;
        rv[i]  = idx >> 5;            // r 0..63
        bcv[i] = (idx & 31) * 4;      // b-chunk
    }

    float4 v[16];
#pragma unroll
    for (int i = 0; i < 16; i++)
        v[i] = *(const float4*)(S5 + (size_t)(rv[i] * 64 + j) * BB + mbase + bcv[i]);

    const int rb0 = warp * 32;

    for (int c = 0; c < TPC; c++) {
        uint32_t* cur = (c & 1) ? Ab1 : Ab0;

        // ---- STS tile c: K-major As[r*136 + b'] ----
#pragma unroll
        for (int i = 0; i < 16; i++) {
            uint32_t* d = cur + rv[i] * 136 + bcv[i];
            d[0] = f2tf32(v[i].x); d[1] = f2tf32(v[i].y);
            d[2] = f2tf32(v[i].z); d[3] = f2tf32(v[i].w);
        }
        if (c + 1 < TPC) {
            const int mb = mbase + (c + 1) * 128;
#pragma unroll
            for (int i = 0; i < 16; i++)
                v[i] = *(const float4*)(S5 + (size_t)(rv[i] * 64 + j) * BB + mb + bcv[i]);
        }
        __syncthreads();

        // ---- MMA: warp tile 32(M=b) x 64(N=s) ----
        float acc[2][8][4] = {};
#pragma unroll
        for (int ks = 0; ks < 8; ks++) {
            const int k0 = ks * 8;
            uint32_t a[2][4];
#pragma unroll
            for (int mi = 0; mi < 2; mi++) {
                const int rb = rb0 + mi * 16;
                a[mi][0] = cur[(k0 + t)     * 136 + rb + g];
                a[mi][1] = cur[(k0 + t)     * 136 + rb + g + 8];
                a[mi][2] = cur[(k0 + t + 4) * 136 + rb + g];
                a[mi][3] = cur[(k0 + t + 4) * 136 + rb + g + 8];
            }
            const int sa = 4 * g;
#pragma unroll
            for (int ni = 0; ni < 8; ni++) {
                const uint32_t b0 = Ws[(ni * 8 + g) * 64 + ((k0 + t)     ^ sa)];
                const uint32_t b1 = Ws[(ni * 8 + g) * 64 + ((k0 + t + 4) ^ sa)];
                mma16n8k8(acc[0][ni], a[0], b0, b1);
                mma16n8k8(acc[1][ni], a[1], b0, b1);
            }
        }

        // ---- natural STG (sector-exact float2): C[b, j*64+s] ----
        float* Cg = C + (size_t)(mbase + c * 128) * NN + j * 64;
#pragma unroll
        for (int mi = 0; mi < 2; mi++) {
            const int r0 = rb0 + mi * 16 + g;
#pragma unroll
            for (int ni = 0; ni < 8; ni++) {
                const int col = ni * 8 + t * 2;
                *(float2*)(Cg + (size_t)r0 * NN + col) =
                    make_float2(acc[mi][ni][0], acc[mi][ni][1]);
                *(float2*)(Cg + (size_t)(r0 + 8) * NN + col) =
                    make_float2(acc[mi][ni][2], acc[mi][ni][3]);
            }
        }
    }
}

// ---------------------------------------------------------------------------
// Final permutation: out[b, s*64 + l] = in[b, l*64 + s].
// ---------------------------------------------------------------------------
__global__ __launch_bounds__(256) void trans64(const float* __restrict__ in,
                                               float* __restrict__ out) {
    __shared__ float smt[64][65];
    const int b   = blockIdx.x;
    const int tid = threadIdx.x;
    const float* ip = in  + (size_t)b * NN;
    float*       op = out + (size_t)b * NN;

#pragma unroll
    for (int i = 0; i < 16; i++) {
        const int t = tid + i * 256;
        smt[t & 63][t >> 6] = ip[t];
    }
    __syncthreads();
#pragma unroll
    for (int i = 0; i < 16; i++) {
        const int t = tid + i * 256;
        op[t] = smt[t >> 6][t & 63];
    }
}

extern "C" void kernel_launch(void* const* d_in, const int* in_sizes, int n_in,
                              void* d_out, int out_size) {
    const float* x  = (const float*)d_in[0];   // (8192, 4096)
    const float* w1 = (const float*)d_in[1];   // (64, 64, 64)
    const float* w2 = (const float*)d_in[2];   // (64, 64, 64)
    float* out = (float*)d_out;

    float *S5 = nullptr, *out2 = nullptr;
    cudaGetSymbolAddress((void**)&S5, g_S5);
    cudaGetSymbolAddress((void**)&out2, g_out2);

    const int smem1 = (2 * 8192 + 4096) * 4;   // 81920
    const int smem2 = (2 * ABW2 + 4096) * 4;   // 86016
    cudaFuncSetAttribute(gemm_s1t, cudaFuncAttributeMaxDynamicSharedMemorySize, smem1);
    cudaFuncSetAttribute(gemm_s2,  cudaFuncAttributeMaxDynamicSharedMemorySize, smem2);

    dim3 ggrid(BB / (128 * TPC), 64);   // (16, 64)

    // Stage 1 (transposed): x -> S5 (feature-major). Mid-permutation absorbed.
    gemm_s1t<<<ggrid, 128, smem1>>>(x, w1, S5);
    // Stage 2: S5 (feature-major read) -> out2 (natural (b, l*64+s)).
    gemm_s2<<<ggrid, 128, smem2>>>(S5, w2, out2);
    // Final permutation: out[b, s*64+l] = out2[b, l*64+s].
    trans64<<<BB, 256>>>(out2, out);
}